// round 1
// baseline (speedup 1.0000x reference)
#include <cuda_runtime.h>

#define FULL 0xFFFFFFFFu

// Problem constants
constexpr int N_RAYS    = 8192;
constexpr int N_SAMPLES = 512;
constexpr int HID       = 32;
constexpr int WARPS_PER_BLOCK = 8;
constexpr int TPT       = 16;   // samples per thread (512 / 32 lanes)

__device__ __forceinline__ float sigmoidf_fast(float x) {
    return __fdividef(1.0f, 1.0f + __expf(-x));
}
__device__ __forceinline__ float softplusf_fast(float x) {
    // stable: max(x,0) + log(1 + exp(-|x|))
    return fmaxf(x, 0.0f) + __logf(1.0f + __expf(-fabsf(x)));
}

__global__ __launch_bounds__(WARPS_PER_BLOCK * 32)
void nerf_render_kernel(
    const float* __restrict__ o,    // [N,3]
    const float* __restrict__ dI,   // [N,3]
    const float* __restrict__ aabb, // [2,3]
    const float* __restrict__ u,    // [N,512]
    const float* __restrict__ W1,   // [3,32]
    const float* __restrict__ b1,   // [32]
    const float* __restrict__ Wc,   // [32,3]
    const float* __restrict__ bc,   // [3]
    const float* __restrict__ Wd,   // [32,1]
    const float* __restrict__ bd,   // [1]
    float* __restrict__ out)        // [N,4]
{
    // ---- weights to shared: sA[j] = (W1[0][j], W1[1][j], W1[2][j], b1[j])
    //                         sB[j] = (Wc[j][0], Wc[j][1], Wc[j][2], Wd[j])
    __shared__ float4 sA[HID];
    __shared__ float4 sB[HID];
    __shared__ float  sbc[4];

    int tx = threadIdx.x;
    if (tx < HID) {
        sA[tx] = make_float4(W1[tx], W1[HID + tx], W1[2 * HID + tx], b1[tx]);
        sB[tx] = make_float4(Wc[3 * tx], Wc[3 * tx + 1], Wc[3 * tx + 2], Wd[tx]);
    }
    if (tx == HID) { sbc[0] = bc[0]; sbc[1] = bc[1]; sbc[2] = bc[2]; sbc[3] = bd[0]; }
    __syncthreads();

    const int warp = tx >> 5;
    const int lane = tx & 31;
    const int r = blockIdx.x * WARPS_PER_BLOCK + warp;

    // ---- ray setup (broadcast loads)
    const float ox = o[3 * r], oy = o[3 * r + 1], oz = o[3 * r + 2];
    const float dx = dI[3 * r], dy = dI[3 * r + 1], dz = dI[3 * r + 2];
    const float mn0 = aabb[0], mn1 = aabb[1], mn2 = aabb[2];
    const float mx0 = aabb[3], mx1 = aabb[4], mx2 = aabb[5];

    // slab test
    float t1, t2;
    t1 = (mn0 - ox) / dx; t2 = (mx0 - ox) / dx;
    float tn = fminf(t1, t2), tf = fmaxf(t1, t2);
    t1 = (mn1 - oy) / dy; t2 = (mx1 - oy) / dy;
    tn = fmaxf(tn, fminf(t1, t2)); tf = fminf(tf, fmaxf(t1, t2));
    t1 = (mn2 - oz) / dz; t2 = (mx2 - oz) / dz;
    tn = fmaxf(tn, fminf(t1, t2)); tf = fminf(tf, fmaxf(t1, t2));
    tn = fmaxf(tn, 0.0f);

    if (!(tn < tf)) {   // inactive ray -> zeros (warp-uniform)
        if (lane == 0) reinterpret_cast<float4*>(out)[r] = make_float4(0.f, 0.f, 0.f, 0.f);
        return;
    }

    const float dnorm  = sqrtf(dx * dx + dy * dy + dz * dz);
    const float scaleT = (tf - tn) * (1.0f / (float)N_SAMPLES);
    const float dscale = scaleT * dnorm;
    const float g0 = 2.0f / (mx0 - mn0);
    const float g1 = 2.0f / (mx1 - mn1);
    const float g2 = 2.0f / (mx2 - mn2);
    const float bcr = sbc[0], bcg = sbc[1], bcb = sbc[2], bdd = sbc[3];

    // ---- load this thread's 16 jitter values + neighbor's first (for last delta)
    const float4* u4 = reinterpret_cast<const float4*>(u + (size_t)r * N_SAMPLES) + lane * 4;
    float4 ua = u4[0], ub = u4[1], uc = u4[2], ud = u4[3];
    float uu[TPT + 1] = { ua.x, ua.y, ua.z, ua.w,  ub.x, ub.y, ub.z, ub.w,
                          uc.x, uc.y, uc.z, uc.w,  ud.x, ud.y, ud.z, ud.w, 0.f };
    uu[TPT] = __shfl_down_sync(FULL, ua.x, 1);   // lane 31's value unused (t==511 path)

    const int base = lane * TPT;

    float e_run = 1.0f;          // running local transmittance  prod exp(-sd)
    float Psum  = 0.0f;          // running local sum of sd
    float ar = 0.f, ag = 0.f, ab = 0.f, aw = 0.f;

    #pragma unroll
    for (int kk = 0; kk < TPT; kk += 2) {
        // ---- per-pair sample geometry
        float n00, n01, n02, n10, n11, n12, dl0, dl1;
        bool ib0, ib1;
        {
            const int t = base + kk;
            const float ucur = uu[kk], unext = uu[kk + 1];
            const float ts = fmaf(scaleT, (float)t + ucur, tn);
            const float x = fmaf(dx, ts, ox), y = fmaf(dy, ts, oy), z = fmaf(dz, ts, oz);
            n00 = fmaf(x - mn0, g0, -1.0f);
            n01 = fmaf(y - mn1, g1, -1.0f);
            n02 = fmaf(z - mn2, g2, -1.0f);
            ib0 = (fabsf(n00) <= 1.0f) & (fabsf(n01) <= 1.0f) & (fabsf(n02) <= 1.0f);
            dl0 = dscale * (1.0f + unext - ucur);
        }
        {
            const int t = base + kk + 1;
            const float ucur = uu[kk + 1], unext = uu[kk + 2];
            const float ts = fmaf(scaleT, (float)t + ucur, tn);
            const float x = fmaf(dx, ts, ox), y = fmaf(dy, ts, oy), z = fmaf(dz, ts, oz);
            n10 = fmaf(x - mn0, g0, -1.0f);
            n11 = fmaf(y - mn1, g1, -1.0f);
            n12 = fmaf(z - mn2, g2, -1.0f);
            ib1 = (fabsf(n10) <= 1.0f) & (fabsf(n11) <= 1.0f) & (fabsf(n12) <= 1.0f);
            dl1 = (t == N_SAMPLES - 1) ? (tf + 1.0f - ts) * dnorm
                                       : dscale * (1.0f + unext - ucur);
        }

        // ---- MLP for both samples, weights loaded once per j
        float c0r = bcr, c0g = bcg, c0b = bcb, d0 = bdd;
        float c1r = bcr, c1g = bcg, c1b = bcb, d1 = bdd;
        #pragma unroll
        for (int j = 0; j < HID; j++) {
            const float4 wa = sA[j];
            float h0 = fmaf(n00, wa.x, fmaf(n01, wa.y, fmaf(n02, wa.z, wa.w)));
            float h1 = fmaf(n10, wa.x, fmaf(n11, wa.y, fmaf(n12, wa.z, wa.w)));
            h0 = fmaxf(h0, 0.0f);
            h1 = fmaxf(h1, 0.0f);
            const float4 wb = sB[j];
            c0r = fmaf(h0, wb.x, c0r); c0g = fmaf(h0, wb.y, c0g);
            c0b = fmaf(h0, wb.z, c0b); d0  = fmaf(h0, wb.w, d0);
            c1r = fmaf(h1, wb.x, c1r); c1g = fmaf(h1, wb.y, c1g);
            c1b = fmaf(h1, wb.z, c1b); d1  = fmaf(h1, wb.w, d1);
        }

        // ---- epilogue sample 0 (order matters for e_run / Psum)
        {
            const float cr = sigmoidf_fast(c0r);
            const float cg = sigmoidf_fast(c0g);
            const float cb = sigmoidf_fast(c0b);
            float den = softplusf_fast(d0);
            if (!ib0) den = 0.0f;
            const float sd  = den * dl0;
            const float esd = __expf(-sd);
            const float wl  = e_run - e_run * esd;   // e_run * (1 - exp(-sd))
            ar = fmaf(wl, cr, ar); ag = fmaf(wl, cg, ag); ab = fmaf(wl, cb, ab);
            aw += wl;
            e_run *= esd;
            Psum  += sd;
        }
        // ---- epilogue sample 1
        {
            const float cr = sigmoidf_fast(c1r);
            const float cg = sigmoidf_fast(c1g);
            const float cb = sigmoidf_fast(c1b);
            float den = softplusf_fast(d1);
            if (!ib1) den = 0.0f;
            const float sd  = den * dl1;
            const float esd = __expf(-sd);
            const float wl  = e_run - e_run * esd;
            ar = fmaf(wl, cr, ar); ag = fmaf(wl, cg, ag); ab = fmaf(wl, cb, ab);
            aw += wl;
            e_run *= esd;
            Psum  += sd;
        }
    }

    // ---- warp exclusive scan of per-thread optical depth -> global transmittance base
    float inc = Psum;
    #pragma unroll
    for (int off = 1; off < 32; off <<= 1) {
        float y = __shfl_up_sync(FULL, inc, off);
        if (lane >= off) inc += y;
    }
    float excl = __shfl_up_sync(FULL, inc, 1);
    if (lane == 0) excl = 0.0f;
    const float sc = __expf(-excl);
    ar *= sc; ag *= sc; ab *= sc; aw *= sc;

    // ---- warp reduction of the 4 accumulators
    #pragma unroll
    for (int off = 16; off > 0; off >>= 1) {
        ar += __shfl_xor_sync(FULL, ar, off);
        ag += __shfl_xor_sync(FULL, ag, off);
        ab += __shfl_xor_sync(FULL, ab, off);
        aw += __shfl_xor_sync(FULL, aw, off);
    }

    if (lane == 0)
        reinterpret_cast<float4*>(out)[r] = make_float4(ar, ag, ab, aw);
}

extern "C" void kernel_launch(void* const* d_in, const int* in_sizes, int n_in,
                              void* d_out, int out_size) {
    const float* o    = (const float*)d_in[0];
    const float* dI   = (const float*)d_in[1];
    const float* aabb = (const float*)d_in[2];
    const float* u    = (const float*)d_in[3];
    const float* W1   = (const float*)d_in[4];
    const float* b1   = (const float*)d_in[5];
    const float* Wc   = (const float*)d_in[6];
    const float* bc   = (const float*)d_in[7];
    const float* Wd   = (const float*)d_in[8];
    const float* bd   = (const float*)d_in[9];
    float* out = (float*)d_out;

    dim3 grid(N_RAYS / WARPS_PER_BLOCK);   // 1024 blocks, one warp per ray
    dim3 block(WARPS_PER_BLOCK * 32);      // 256 threads
    nerf_render_kernel<<<grid, block>>>(o, dI, aabb, u, W1, b1, Wc, bc, Wd, bd, out);
}